// round 15
// baseline (speedup 1.0000x reference)
#include <cuda_runtime.h>
#include <cuda_bf16.h>
#include <cstdint>
#include <cstddef>

// Problem constants
constexpr int BB  = 8;
constexpr int SS  = 4096;
constexpr int DD  = 1024;
constexpr int HH  = 16;
constexpr int DHH = 64;
constexpr int MTOK = BB * SS;          // 32768 tokens
constexpr int D3   = 3 * DD;           // fused QKV output width

// ---------------------------------------------------------------------------
// Scratch (device globals: no allocation allowed anywhere)
// 3-product split precision: C = Ahi*Bhi + Alo*Bhi + Ahi*Blo
// stored as separate hi/lo arrays (K = 1024 each)
// ---------------------------------------------------------------------------
__device__ float g_qkv[(size_t)MTOK * D3];              // [m][q|k|v] fp32
__device__ __nv_bfloat16 g_xhi[(size_t)MTOK * DD];
__device__ __nv_bfloat16 g_xlo[(size_t)MTOK * DD];
__device__ __nv_bfloat16 g_chi[(size_t)MTOK * DD];      // ctx hi
__device__ __nv_bfloat16 g_clo[(size_t)MTOK * DD];      // ctx lo
__device__ __nv_bfloat16 g_wqkvhi[(size_t)D3 * DD];     // [wq;wk;wv] hi
__device__ __nv_bfloat16 g_wqkvlo[(size_t)D3 * DD];
__device__ __nv_bfloat16 g_wohi[(size_t)DD * DD];
__device__ __nv_bfloat16 g_wolo[(size_t)DD * DD];

// ---------------------------------------------------------------------------
// Helpers
// ---------------------------------------------------------------------------
__device__ __forceinline__ uint32_t smem_u32(const void* p) {
    uint32_t a;
    asm("{ .reg .u64 t; cvta.to.shared.u64 t, %1; cvt.u32.u64 %0, t; }"
        : "=r"(a) : "l"(p));
    return a;
}

__device__ __forceinline__ void cp16(uint32_t dst, const void* src) {
    asm volatile("cp.async.cg.shared.global [%0], [%1], 16;"
                 :: "r"(dst), "l"(src) : "memory");
}

__device__ __forceinline__ uint32_t swz(uint32_t off) {
    return off ^ ((off >> 3) & 0x70);   // SW128 within 1024B blocks
}

__device__ __forceinline__ void ldsm4(uint32_t r[4], uint32_t addr) {
    asm volatile("ldmatrix.sync.aligned.m8n8.x4.shared.b16 {%0,%1,%2,%3}, [%4];"
                 : "=r"(r[0]), "=r"(r[1]), "=r"(r[2]), "=r"(r[3]) : "r"(addr));
}

__device__ __forceinline__ void mma16816(float d[4], const uint32_t a[4],
                                         uint32_t b0, uint32_t b1) {
    asm volatile(
        "mma.sync.aligned.m16n8k16.row.col.f32.bf16.bf16.f32 "
        "{%0,%1,%2,%3}, {%4,%5,%6,%7}, {%8,%9}, {%0,%1,%2,%3};"
        : "+f"(d[0]), "+f"(d[1]), "+f"(d[2]), "+f"(d[3])
        : "r"(a[0]), "r"(a[1]), "r"(a[2]), "r"(a[3]), "r"(b0), "r"(b1));
}

// ---------------------------------------------------------------------------
// Split-precision conversion: fp32 -> (hi, lo) bf16 arrays
// ---------------------------------------------------------------------------
struct alignas(16) B8 { __nv_bfloat16 v[8]; };

__device__ __forceinline__ void split_body(const float* __restrict__ src,
                                           __nv_bfloat16* __restrict__ dhi,
                                           __nv_bfloat16* __restrict__ dlo,
                                           size_t idx)
{
    const float4 a = *(const float4*)(src + idx);
    const float4 b = *(const float4*)(src + idx + 4);
    float f[8] = {a.x, a.y, a.z, a.w, b.x, b.y, b.z, b.w};
    B8 ph, pl;
    #pragma unroll
    for (int i = 0; i < 8; i++) {
        __nv_bfloat16 h = __float2bfloat16(f[i]);
        ph.v[i] = h;
        pl.v[i] = __float2bfloat16(f[i] - __bfloat162float(h));
    }
    *(B8*)(dhi + idx) = ph;
    *(B8*)(dlo + idx) = pl;
}

// One launch: activation split (blocks 0..16383) + 4 weight splits (512 each)
constexpr int ACT_BLOCKS = (int)(((size_t)MTOK * DD / 8) / 256);  // 16384
constexpr int WT_BLOCKS  = (int)(((size_t)DD * DD / 8) / 256);    // 512

__global__ __launch_bounds__(256)
void split_all(const float* __restrict__ x,
               const float* __restrict__ wq, const float* __restrict__ wk,
               const float* __restrict__ wv, const float* __restrict__ wo,
               __nv_bfloat16* __restrict__ xhi, __nv_bfloat16* __restrict__ xlo,
               __nv_bfloat16* __restrict__ whi, __nv_bfloat16* __restrict__ wlo,
               __nv_bfloat16* __restrict__ wohi, __nv_bfloat16* __restrict__ wolo)
{
    const int b = blockIdx.x;
    if (b < ACT_BLOCKS) {
        const size_t idx = ((size_t)b * 256 + threadIdx.x) * 8;
        split_body(x, xhi, xlo, idx);
    } else {
        const int wb  = b - ACT_BLOCKS;
        const int sel = wb >> 9;                 // 0..3
        const float* src = (sel == 0) ? wq : (sel == 1) ? wk : (sel == 2) ? wv : wo;
        __nv_bfloat16* dh = (sel == 3) ? wohi : whi + (size_t)sel * DD * DD;
        __nv_bfloat16* dl = (sel == 3) ? wolo : wlo + (size_t)sel * DD * DD;
        const size_t idx = ((size_t)(wb & 511) * 256 + threadIdx.x) * 8;
        split_body(src, dh, dl, idx);
    }
}

// ---------------------------------------------------------------------------
// bf16 mma.sync GEMM (NT), 3-product split:
//   C[m][n] = sum_k Ahi*Bhi + Alo*Bhi + Ahi*Blo + bias[n]
// 48 chunks of BK=64: phase = chunk/16 selects (A,B) source arrays.
// Tile 128x256, SW128, 8 warps (2x4) of 64x64, 4-stage cp.async pipeline.
// Warp k-step skew: warps 4-7 walk k16-steps in order (2,3,0,1) so the two
// warps on each SMSP anti-phase their LDSM bursts against HMMA issue.
// ---------------------------------------------------------------------------
constexpr int GBM = 128, GBN = 256, GBK = 64;
constexpr int STAGES = 4;
constexpr int NCH = 48;                       // 3 phases x 16 chunks
constexpr int ASZ = GBM * 128;                // 16384 B / stage
constexpr int BSZ = GBN * 128;                // 32768 B / stage
constexpr int STG = ASZ + BSZ;                // 49152
constexpr int GEMM_SMEM = STAGES * STG;       // 196608

__global__ __launch_bounds__(256, 1)
void gemm_mma(const __nv_bfloat16* __restrict__ Ahi,
              const __nv_bfloat16* __restrict__ Alo,
              const __nv_bfloat16* __restrict__ Bhi,
              const __nv_bfloat16* __restrict__ Blo,
              const float* __restrict__ b0p,
              const float* __restrict__ b1p,
              const float* __restrict__ b2p,
              float* __restrict__ C, int ldc)
{
    extern __shared__ char smem[];
    const uint32_t sb = smem_u32(smem);
    const int tid  = threadIdx.x;
    const int wid  = tid >> 5;
    const int lane = tid & 31;
    const int m0 = blockIdx.y * GBM;
    const int n0 = blockIdx.x * GBN;
    const int wm = (wid >> 2) * 64;           // warp m offset in tile
    const int wn = (wid & 3) * 64;            // warp n offset in tile

    float acc[4][8][4];
    #pragma unroll
    for (int i = 0; i < 4; i++)
        #pragma unroll
        for (int j = 0; j < 8; j++)
            #pragma unroll
            for (int c = 0; c < 4; c++) acc[i][j][c] = 0.0f;

    auto load_stage = [&](int i, int s) {
        const int phase = i >> 4;                     // 0,1,2
        const int k0 = (i & 15) * GBK;
        const __nv_bfloat16* Asrc = (phase == 1) ? Alo : Ahi;
        const __nv_bfloat16* Bsrc = (phase == 2) ? Blo : Bhi;
        const uint32_t ab = sb + s * STG;
        const uint32_t bb = ab + ASZ;
        #pragma unroll
        for (int j = 0; j < 12; j++) {
            const int c  = tid + j * 256;
            const int cc = c & 7;
            if (c < 1024) {
                const int r = c >> 3;          // A rows 0..127
                cp16(ab + swz((uint32_t)(r * 128 + cc * 16)),
                     Asrc + (size_t)(m0 + r) * DD + k0 + cc * 8);
            } else {
                const int r = (c - 1024) >> 3; // B rows 0..255
                cp16(bb + swz((uint32_t)(r * 128 + cc * 16)),
                     Bsrc + (size_t)(n0 + r) * DD + k0 + cc * 8);
            }
        }
        asm volatile("cp.async.commit_group;" ::: "memory");
    };

    // 3-deep prologue -> 2-chunk prefetch distance in steady state
    load_stage(0, 0);
    load_stage(1, 1);
    load_stage(2, 2);

    // ldmatrix per-lane source rows (validated fragment mapping)
    const int arow = wm + (lane & 15);
    const int akb  = (lane >> 4) * 16;
    const int brow = wn + (lane & 7) + ((lane >> 4) << 3);
    const int bkb  = ((lane >> 3) & 1) * 16;
    const int skew = ((wid >> 2) & 1) << 1;   // warps 4-7 start at k-step 2

    #pragma unroll 4
    for (int i = 0; i < NCH; i++) {
        asm volatile("cp.async.wait_group 2;" ::: "memory");
        __syncthreads();
        const int s = i % STAGES;
        const uint32_t ab = sb + s * STG;
        const uint32_t bb = ab + ASZ;

        #pragma unroll
        for (int t = 0; t < 4; t++) {
            const int kk = (t + skew) & 3;     // anti-phased between SMSP warp pairs
            const int c0 = kk * 32;
            uint32_t af[4][4], bf[4][4];
            #pragma unroll
            for (int mi = 0; mi < 4; mi++)
                ldsm4(af[mi], ab + swz((uint32_t)((arow + mi * 16) * 128 + c0 + akb)));
            #pragma unroll
            for (int nj = 0; nj < 4; nj++)
                ldsm4(bf[nj], bb + swz((uint32_t)((brow + nj * 16) * 128 + c0 + bkb)));
            #pragma unroll
            for (int mi = 0; mi < 4; mi++)
                #pragma unroll
                for (int nj = 0; nj < 4; nj++) {
                    mma16816(acc[mi][2 * nj],     af[mi], bf[nj][0], bf[nj][1]);
                    mma16816(acc[mi][2 * nj + 1], af[mi], bf[nj][2], bf[nj][3]);
                }
        }
        if (i + 3 < NCH) load_stage(i + 3, (i + 3) % STAGES);
    }

    // Epilogue: bias per 1024-column group (fused QKV), float2 stores
    const int sel = n0 >> 10;
    const float* bias = (sel == 0) ? b0p : (sel == 1) ? b1p : b2p;
    const int rbase = m0 + wm + (lane >> 2);
    const int cbase = n0 + wn + 2 * (lane & 3);          // C column
    const int bbase = (n0 & 1023) + wn + 2 * (lane & 3); // bias column
    float2 bb2[8];
    #pragma unroll
    for (int nj = 0; nj < 8; nj++) {
        bb2[nj].x = bias[bbase + nj * 8];
        bb2[nj].y = bias[bbase + nj * 8 + 1];
    }
    #pragma unroll
    for (int mi = 0; mi < 4; mi++) {
        #pragma unroll
        for (int nj = 0; nj < 8; nj++) {
            const int cc = cbase + nj * 8;
            float2 v0 = { acc[mi][nj][0] + bb2[nj].x, acc[mi][nj][1] + bb2[nj].y };
            float2 v1 = { acc[mi][nj][2] + bb2[nj].x, acc[mi][nj][3] + bb2[nj].y };
            *(float2*)(C + (size_t)(rbase + mi * 16)     * ldc + cc) = v0;
            *(float2*)(C + (size_t)(rbase + mi * 16 + 8) * ldc + cc) = v1;
        }
    }
}

// ---------------------------------------------------------------------------
// Per-token attention over the HEAD axis + fused hi/lo bf16 ctx emission.
// ---------------------------------------------------------------------------
constexpr int WPB = 2;
constexpr int RPAD = 68;

__global__ __launch_bounds__(WPB * 32)
void attn_kernel(const float* __restrict__ qkv,
                 __nv_bfloat16* __restrict__ chi,
                 __nv_bfloat16* __restrict__ clo)
{
    __shared__ float sq[WPB][HH * RPAD];
    __shared__ float sk[WPB][HH * RPAD];
    __shared__ float sv[WPB][HH * RPAD];
    __shared__ float sp[WPB][HH][17];

    const int w    = threadIdx.x >> 5;
    const int lane = threadIdx.x & 31;
    const size_t token = (size_t)blockIdx.x * WPB + w;

    const float* qt = qkv + token * D3;
    const float* kt = qt + DD;
    const float* vt = qt + 2 * DD;

    #pragma unroll
    for (int i = 0; i < 8; i++) {
        const int e   = i * 128 + lane * 4;
        const int row = e >> 6;
        const int col = e & 63;
        *(float4*)&sq[w][row * RPAD + col] = *(const float4*)(qt + e);
        *(float4*)&sk[w][row * RPAD + col] = *(const float4*)(kt + e);
        *(float4*)&sv[w][row * RPAD + col] = *(const float4*)(vt + e);
    }
    __syncwarp();

    // Scores: lane owns k-row g = lane&15 (register-cached), 8 h values
    {
        const int g  = lane & 15;
        const int lh = lane >> 4;
        float4 kreg[16];
        #pragma unroll
        for (int j = 0; j < 16; j++)
            kreg[j] = *(const float4*)&sk[w][g * RPAD + 4 * j];
        float accv[8];
        #pragma unroll
        for (int i = 0; i < 8; i++) accv[i] = 0.0f;
        #pragma unroll
        for (int j = 0; j < 16; j++) {
            #pragma unroll
            for (int i = 0; i < 8; i++) {
                const float4 q4 = *(const float4*)&sq[w][(2 * i + lh) * RPAD + 4 * j];
                float t = q4.x * kreg[j].x;
                t = fmaf(q4.y, kreg[j].y, t);
                t = fmaf(q4.z, kreg[j].z, t);
                t = fmaf(q4.w, kreg[j].w, t);
                accv[i] += t;
            }
        }
        #pragma unroll
        for (int i = 0; i < 8; i++)
            sp[w][2 * i + lh][g] = accv[i] * 0.125f;
    }
    __syncwarp();

    if (lane < HH) {
        float mx = -1e30f;
        #pragma unroll
        for (int g = 0; g < HH; g++) mx = fmaxf(mx, sp[w][lane][g]);
        float e[HH];
        float s = 0.0f;
        #pragma unroll
        for (int g = 0; g < HH; g++) { e[g] = __expf(sp[w][lane][g] - mx); s += e[g]; }
        const float inv = 1.0f / s;
        #pragma unroll
        for (int g = 0; g < HH; g++) sp[w][lane][g] = e[g] * inv;
    }
    __syncwarp();

    // Ctx: register-cache the lane's two v columns (d = 2*lane, 2*lane+1)
    float vr0[HH], vr1[HH];
    #pragma unroll
    for (int g = 0; g < HH; g++) {
        const float2 vv = *(const float2*)&sv[w][g * RPAD + 2 * lane];
        vr0[g] = vv.x; vr1[g] = vv.y;
    }
    __nv_bfloat16* hrow = chi + token * DD;
    __nv_bfloat16* lrow = clo + token * DD;
    #pragma unroll
    for (int h = 0; h < HH; h++) {
        float a0 = 0.0f, a1 = 0.0f;
        #pragma unroll
        for (int g = 0; g < HH; g++) {
            const float p = sp[w][h][g];   // warp-wide broadcast read
            a0 = fmaf(p, vr0[g], a0);
            a1 = fmaf(p, vr1[g], a1);
        }
        const __nv_bfloat16 h0 = __float2bfloat16(a0);
        const __nv_bfloat16 h1 = __float2bfloat16(a1);
        const __nv_bfloat16 l0 = __float2bfloat16(a0 - __bfloat162float(h0));
        const __nv_bfloat16 l1 = __float2bfloat16(a1 - __bfloat162float(h1));
        __nv_bfloat162 hp, lp;
        hp.x = h0; hp.y = h1;
        lp.x = l0; lp.y = l1;
        const int col = h * DHH + 2 * lane;
        *(__nv_bfloat162*)(hrow + col) = hp;
        *(__nv_bfloat162*)(lrow + col) = lp;
    }
}

// ---------------------------------------------------------------------------
// Launch
// ---------------------------------------------------------------------------
extern "C" void kernel_launch(void* const* d_in, const int* in_sizes, int n_in,
                              void* d_out, int out_size)
{
    const float* x  = (const float*)d_in[0];
    const float* wq = (const float*)d_in[1];
    const float* bq = (const float*)d_in[2];
    const float* wk = (const float*)d_in[3];
    const float* bk = (const float*)d_in[4];
    const float* wv = (const float*)d_in[5];
    const float* bv = (const float*)d_in[6];
    const float* wo = (const float*)d_in[7];
    const float* bo = (const float*)d_in[8];
    float* out = (float*)d_out;

    float *qkv;
    __nv_bfloat16 *xhi, *xlo, *chi, *clo, *wqkvhi, *wqkvlo, *wohi, *wolo;
    cudaGetSymbolAddress((void**)&qkv,    g_qkv);
    cudaGetSymbolAddress((void**)&xhi,    g_xhi);
    cudaGetSymbolAddress((void**)&xlo,    g_xlo);
    cudaGetSymbolAddress((void**)&chi,    g_chi);
    cudaGetSymbolAddress((void**)&clo,    g_clo);
    cudaGetSymbolAddress((void**)&wqkvhi, g_wqkvhi);
    cudaGetSymbolAddress((void**)&wqkvlo, g_wqkvlo);
    cudaGetSymbolAddress((void**)&wohi,   g_wohi);
    cudaGetSymbolAddress((void**)&wolo,   g_wolo);

    cudaFuncSetAttribute(gemm_mma,
                         cudaFuncAttributeMaxDynamicSharedMemorySize, GEMM_SMEM);

    // All splits in one launch
    split_all<<<ACT_BLOCKS + 4 * WT_BLOCKS, 256>>>(
        x, wq, wk, wv, wo, xhi, xlo, wqkvhi, wqkvlo, wohi, wolo);

    // Fused QKV GEMM: N = 3072
    dim3 gq(D3 / GBN, MTOK / GBM);   // (12, 256)
    gemm_mma<<<gq, 256, GEMM_SMEM>>>(xhi, xlo, wqkvhi, wqkvlo,
                                     bq, bk, bv, qkv, D3);

    attn_kernel<<<MTOK / WPB, WPB * 32>>>(qkv, chi, clo);

    // Output GEMM: N = 1024
    dim3 go(DD / GBN, MTOK / GBM);   // (4, 256)
    gemm_mma<<<go, 256, GEMM_SMEM>>>(chi, clo, wohi, wolo,
                                     bo, bo, bo, out, DD);
}